// round 3
// baseline (speedup 1.0000x reference)
#include <cuda_runtime.h>
#include <cstdint>

// Problem constants
#define B_ 2
#define L_ 2048
#define S_ 2048
#define H_ 8
#define E_ 64
#define D_ 64

constexpr float SCALE_ = 0.125f;      // 1/sqrt(64)
constexpr float EPS_   = 1e-8f;
constexpr int BM = 64;
constexpr int BN = 64;
constexpr int NTHREADS = 256;         // 16 x 16 thread grid
constexpr int NBLOCKS = B_ * H_ * (L_ / BM);   // 512
constexpr int OUT_OFF = B_ * L_ * H_ * D_;
constexpr float REG_NORM = 0.5f / ((float)B_ * H_ * L_ * S_);

typedef unsigned long long u64;

// Packed fp32x2 FMA (Blackwell FFMA2 — only reachable via PTX)
#define FMA2(d,a,b)    asm("fma.rn.f32x2 %0, %1, %2, %3;" : "=l"(d) : "l"(a), "l"(b), "l"(d))
#define UNPACK2(x,y,d) asm("mov.b64 {%0, %1}, %2;" : "=f"(x), "=f"(y) : "l"(d))

__device__ float g_reg_partials[NBLOCKS];

// Shared memory layout (floats)
// QP/KP: interleaved e-pair layout: QP[e2][2r+p] = Q[r][2*e2+p]
constexpr int OFF_QP  = 0;            // [32][128] = 4096
constexpr int OFF_KP  = 4096;         // [32][128] = 4096
constexpr int OFF_VD  = 8192;         // [64][64]  = 4096 row-major
constexpr int OFF_VW  = 12288;        // [64][64]  = 4096
constexpr int OFF_PDD = 16384;        // [64][128] = 8192 duplicated P (dot)
constexpr int OFF_PWD = 24576;        // [64][128] = 8192 duplicated P (wedge)
constexpr int OFF_QN  = 32768;        // [64][4]
constexpr int OFF_KN  = 33024;        // [64][4]
constexpr int OFF_RED = 33280;        // [256]
constexpr int SMEM_FLOATS = 33536;
constexpr int SMEM_BYTES = SMEM_FLOATS * 4;   // 134144 B -> 1 CTA/SM

__global__ void __launch_bounds__(NTHREADS, 1)
dual_path_attn_kernel(const float* __restrict__ gq,
                      const float* __restrict__ gk,
                      const float* __restrict__ gvd,
                      const float* __restrict__ gvw,
                      const float* __restrict__ gfg,
                      float* __restrict__ out)
{
    extern __shared__ float sm[];
    float* QP = sm + OFF_QP;
    float* KP = sm + OFF_KP;
    float* VD = sm + OFF_VD;
    float* VW = sm + OFF_VW;
    float* PDD = sm + OFF_PDD;
    float* PWD = sm + OFF_PWD;
    float* QN = sm + OFF_QN;
    float* KN = sm + OFF_KN;
    float* RED = sm + OFF_RED;

    const int tid = threadIdx.x;
    const int tx = tid & 15;          // key-col / d-col group
    const int ty = tid >> 4;          // query-row group

    const int bid = blockIdx.x;
    const int mb = bid & 31;          // L/BM = 32
    const int bh = bid >> 5;
    const int h  = bh & 7;
    const int b  = bh >> 3;
    const int l0 = mb * BM;

    // Loader mapping: 4 threads per row, each covers 16 consecutive floats
    const int lr = tid >> 2;          // row 0..63
    const int lp = tid & 3;           // part 0..3
    const int lc = lp << 4;           // col 0,16,32,48

    // ---- Load Q into pair layout + qn2 partials ----
    {
        const float* src = gq + ((((size_t)b * L_ + l0 + lr) * H_ + h) << 6) + lc;
        float ss = 0.f;
        #pragma unroll
        for (int u = 0; u < 4; u++) {
            float4 v = *(const float4*)(src + u * 4);
            int e2 = (lc + u * 4) >> 1;          // even
            *(float2*)(QP + e2 * 128 + 2 * lr)       = make_float2(v.x, v.y);
            *(float2*)(QP + (e2 + 1) * 128 + 2 * lr) = make_float2(v.z, v.w);
            ss += v.x * v.x + v.y * v.y + v.z * v.z + v.w * v.w;
        }
        QN[lr * 4 + lp] = ss;
    }
    __syncthreads();

    float qn2r[4];
    #pragma unroll
    for (int i = 0; i < 4; i++) {
        int r = ty * 4 + i;
        qn2r[i] = QN[r * 4 + 0] + QN[r * 4 + 1] + QN[r * 4 + 2] + QN[r * 4 + 3];
    }

    // Output accumulators (f32x2 pairs over d), softmax denominators.
    // No max subtraction needed: |scores| bounded ~20, fp32 sums safe.
    float l_d[4], l_w[4];
    u64 od2[4][2], ow2[4][2];
    #pragma unroll
    for (int i = 0; i < 4; i++) {
        l_d[i] = 0.f; l_w[i] = 0.f;
        od2[i][0] = 0ull; od2[i][1] = 0ull;
        ow2[i][0] = 0ull; ow2[i][1] = 0ull;
    }
    float regd = 0.f, regw = 0.f;

    for (int s0 = 0; s0 < S_; s0 += BN) {
        __syncthreads();   // previous iteration's readers done before overwrite

        // ---- Stage K (pair layout) + kn2, Vd/Vw (row-major) ----
        {
            const size_t rowbase = (((size_t)b * S_ + s0 + lr) * H_ + h) << 6;
            const float* ksrc = gk + rowbase + lc;
            float ss = 0.f;
            #pragma unroll
            for (int u = 0; u < 4; u++) {
                float4 v = *(const float4*)(ksrc + u * 4);
                int e2 = (lc + u * 4) >> 1;
                *(float2*)(KP + e2 * 128 + 2 * lr)       = make_float2(v.x, v.y);
                *(float2*)(KP + (e2 + 1) * 128 + 2 * lr) = make_float2(v.z, v.w);
                ss += v.x * v.x + v.y * v.y + v.z * v.z + v.w * v.w;
            }
            KN[lr * 4 + lp] = ss;

            const float* vdsrc = gvd + rowbase + lc;
            const float* vwsrc = gvw + rowbase + lc;
            #pragma unroll
            for (int u = 0; u < 4; u++) {
                *(float4*)(VD + lr * 64 + lc + u * 4) = *(const float4*)(vdsrc + u * 4);
                *(float4*)(VW + lr * 64 + lc + u * 4) = *(const float4*)(vwsrc + u * 4);
            }
        }
        __syncthreads();

        float kn2r[4];
        #pragma unroll
        for (int j = 0; j < 4; j++) {
            int c = tx * 4 + j;
            kn2r[j] = KN[c * 4 + 0] + KN[c * 4 + 1] + KN[c * 4 + 2] + KN[c * 4 + 3];
        }

        // ---- Score GEMM: pairs over e, zero movs ----
        // acc2[i][j] = (sum over even e, sum over odd e) of q_i[e]*k_j[e]
        u64 acc2[4][4];
        #pragma unroll
        for (int i = 0; i < 4; i++)
            #pragma unroll
            for (int j = 0; j < 4; j++) acc2[i][j] = 0ull;

        #pragma unroll 8
        for (int e2 = 0; e2 < 32; e2++) {
            ulonglong2 qa = *(const ulonglong2*)(QP + e2 * 128 + 8 * ty);      // rows r0,r1
            ulonglong2 qb = *(const ulonglong2*)(QP + e2 * 128 + 8 * ty + 4);  // rows r2,r3
            ulonglong2 ka = *(const ulonglong2*)(KP + e2 * 128 + 8 * tx);      // cols c0,c1
            ulonglong2 kb = *(const ulonglong2*)(KP + e2 * 128 + 8 * tx + 4);  // cols c2,c3
            u64 q[4] = {qa.x, qa.y, qb.x, qb.y};
            u64 k[4] = {ka.x, ka.y, kb.x, kb.y};
            #pragma unroll
            for (int i = 0; i < 4; i++) {
                FMA2(acc2[i][0], q[i], k[0]);
                FMA2(acc2[i][1], q[i], k[1]);
                FMA2(acc2[i][2], q[i], k[2]);
                FMA2(acc2[i][3], q[i], k[3]);
            }
        }

        // ---- Transform: scores -> exp (no max), store duplicated P tiles ----
        #pragma unroll
        for (int i = 0; i < 4; i++) {
            float pd[4], pw[4];
            #pragma unroll
            for (int j = 0; j < 4; j++) {
                float xe, xo;
                UNPACK2(xe, xo, acc2[i][j]);
                float d0 = xe + xo;                              // raw dot
                float w2 = fmaxf(fmaf(-d0, d0, qn2r[i] * kn2r[j]), 0.f) + EPS_;
                float wr = sqrtf(w2);                            // raw wedge
                pd[j] = __expf(d0 * SCALE_);
                pw[j] = __expf(wr * SCALE_);
                regd += fabsf(d0);
                regw += wr;
            }
            l_d[i] += (pd[0] + pd[1]) + (pd[2] + pd[3]);
            l_w[i] += (pw[0] + pw[1]) + (pw[2] + pw[3]);
            float* pdd = PDD + (ty * 4 + i) * 128 + 8 * tx;
            float* pwd = PWD + (ty * 4 + i) * 128 + 8 * tx;
            *(float4*)(pdd)     = make_float4(pd[0], pd[0], pd[1], pd[1]);
            *(float4*)(pdd + 4) = make_float4(pd[2], pd[2], pd[3], pd[3]);
            *(float4*)(pwd)     = make_float4(pw[0], pw[0], pw[1], pw[1]);
            *(float4*)(pwd + 4) = make_float4(pw[2], pw[2], pw[3], pw[3]);
        }
        __syncthreads();

        // ---- P·V GEMMs: dup-pairs from smem, zero movs ----
        #pragma unroll 4
        for (int sp = 0; sp < 32; sp++) {
            const int s = sp * 2;
            ulonglong2 vd0 = *(const ulonglong2*)(VD + s * 64 + tx * 4);        // row s
            ulonglong2 vd1 = *(const ulonglong2*)(VD + s * 64 + 64 + tx * 4);   // row s+1
            ulonglong2 vw0 = *(const ulonglong2*)(VW + s * 64 + tx * 4);
            ulonglong2 vw1 = *(const ulonglong2*)(VW + s * 64 + 64 + tx * 4);
            #pragma unroll
            for (int i = 0; i < 4; i++) {
                // .x = dup(P[row][s]), .y = dup(P[row][s+1])
                ulonglong2 pdp = *(const ulonglong2*)(PDD + (ty * 4 + i) * 128 + 4 * sp);
                FMA2(od2[i][0], pdp.x, vd0.x);
                FMA2(od2[i][1], pdp.x, vd0.y);
                FMA2(od2[i][0], pdp.y, vd1.x);
                FMA2(od2[i][1], pdp.y, vd1.y);
                ulonglong2 pwp = *(const ulonglong2*)(PWD + (ty * 4 + i) * 128 + 4 * sp);
                FMA2(ow2[i][0], pwp.x, vw0.x);
                FMA2(ow2[i][1], pwp.x, vw0.y);
                FMA2(ow2[i][0], pwp.y, vw1.x);
                FMA2(ow2[i][1], pwp.y, vw1.y);
            }
        }
    }

    // ---- Reduce row denominators across the 16 tx lanes ----
    #pragma unroll
    for (int i = 0; i < 4; i++) {
        #pragma unroll
        for (int off = 8; off >= 1; off >>= 1) {
            l_d[i] += __shfl_xor_sync(0xffffffffu, l_d[i], off);
            l_w[i] += __shfl_xor_sync(0xffffffffu, l_w[i], off);
        }
    }

    // ---- Epilogue ----
    const float fg = *gfg;
    const float g = 1.f / (1.f + __expf(-fg));
    const float og = 1.f - g;
    #pragma unroll
    for (int i = 0; i < 4; i++) {
        float sd = og / l_d[i];
        float sw = g / l_w[i];
        float a0, a1, a2, a3, b0, b1, b2, b3;
        UNPACK2(a0, a1, od2[i][0]);
        UNPACK2(a2, a3, od2[i][1]);
        UNPACK2(b0, b1, ow2[i][0]);
        UNPACK2(b2, b3, ow2[i][1]);
        float4 o;
        o.x = a0 * sd + b0 * sw;
        o.y = a1 * sd + b1 * sw;
        o.z = a2 * sd + b2 * sw;
        o.w = a3 * sd + b3 * sw;
        size_t oidx = ((((size_t)b * L_ + l0 + ty * 4 + i) * H_ + h) << 6) + tx * 4;
        *(float4*)(out + oidx) = o;
    }

    // ---- Block-reduce regularizer partial (deterministic) ----
    RED[tid] = (regd + regw) * SCALE_;   // both paths scaled by 1/8
    __syncthreads();
    #pragma unroll
    for (int off = 128; off > 0; off >>= 1) {
        if (tid < off) RED[tid] += RED[tid + off];
        __syncthreads();
    }
    if (tid == 0) g_reg_partials[bid] = RED[0];
}

__global__ void finalize_reg_kernel(float* __restrict__ out)
{
    __shared__ float s[256];
    int tid = threadIdx.x;
    s[tid] = g_reg_partials[tid] + g_reg_partials[tid + 256];
    __syncthreads();
    #pragma unroll
    for (int off = 128; off > 0; off >>= 1) {
        if (tid < off) s[tid] += s[tid + off];
        __syncthreads();
    }
    if (tid == 0) out[OUT_OFF] = s[0] * REG_NORM;
}

extern "C" void kernel_launch(void* const* d_in, const int* in_sizes, int n_in,
                              void* d_out, int out_size)
{
    const float* gq  = (const float*)d_in[0];
    const float* gk  = (const float*)d_in[1];
    const float* gvd = (const float*)d_in[2];
    const float* gvw = (const float*)d_in[3];
    const float* gfg = (const float*)d_in[4];
    float* out = (float*)d_out;

    static bool attr_set = false;
    if (!attr_set) {
        cudaFuncSetAttribute(dual_path_attn_kernel,
                             cudaFuncAttributeMaxDynamicSharedMemorySize, SMEM_BYTES);
        attr_set = true;
    }

    dual_path_attn_kernel<<<NBLOCKS, NTHREADS, SMEM_BYTES>>>(gq, gk, gvd, gvw, gfg, out);
    finalize_reg_kernel<<<1, 256>>>(out);
}

// round 5
// speedup vs baseline: 2.6537x; 2.6537x over previous
#include <cuda_runtime.h>
#include <cuda_bf16.h>
#include <cstdint>

// Problem constants
#define B_ 2
#define L_ 2048
#define S_ 2048
#define H_ 8

constexpr int BM = 128;               // query rows per CTA
constexpr int NT = 256;               // 8 warps
constexpr int NBLOCKS = B_ * H_ * (L_ / BM);   // 256
constexpr int OUT_OFF = B_ * L_ * H_ * 64;
constexpr float REG_NORM = 0.5f / ((float)B_ * H_ * L_ * S_);
constexpr float SCALE_ = 0.125f;
constexpr float EPS_   = 1e-8f;
constexpr int STR = 72;               // bf16 row stride (144 B, conflict-free ldmatrix)

// Shared memory byte offsets
constexpr int QHI = 0;                 // [128][72] bf16 = 18432
constexpr int QLO = 18432;
constexpr int KHI = 36864;             // [64][72] = 9216
constexpr int KLO = 46080;
constexpr int VDH = 55296;             // Vd [s][d] hi/lo
constexpr int VDL = 64512;
constexpr int VWH = 73728;
constexpr int VWL = 82944;
constexpr int PDH = 92160;             // P dot [128][72] hi/lo
constexpr int PDL = 110592;
constexpr int PWH = 129024;
constexpr int PWL = 147456;
constexpr int SM_QN = 165888;          // 128 f32
constexpr int SM_KN = 166400;          // 64 f32
constexpr int SM_LD = 166656;          // [2][128] f32 (per col-half row sums)
constexpr int SM_LW = 167680;          // [2][128] f32
constexpr int SM_RED = 168704;         // 256 f32
constexpr int SMEM_BYTES = 169728;

__device__ float g_reg_partials[NBLOCKS];

__device__ __forceinline__ uint32_t smem_u32(const void* p) {
    uint32_t a;
    asm("{ .reg .u64 t; cvta.to.shared.u64 t, %1; cvt.u32.u64 %0, t; }" : "=r"(a) : "l"(p));
    return a;
}

#define LDSM4(r0,r1,r2,r3,addr) \
    asm volatile("ldmatrix.sync.aligned.m8n8.x4.shared.b16 {%0,%1,%2,%3}, [%4];" \
        : "=r"(r0), "=r"(r1), "=r"(r2), "=r"(r3) : "r"(addr))

#define LDSM4T(r0,r1,r2,r3,addr) \
    asm volatile("ldmatrix.sync.aligned.m8n8.x4.trans.shared.b16 {%0,%1,%2,%3}, [%4];" \
        : "=r"(r0), "=r"(r1), "=r"(r2), "=r"(r3) : "r"(addr))

#define MMA16816(d,a,b) \
    asm volatile("mma.sync.aligned.m16n8k16.row.col.f32.bf16.bf16.f32 " \
        "{%0,%1,%2,%3}, {%4,%5,%6,%7}, {%8,%9}, {%0,%1,%2,%3};" \
        : "+f"((d)[0]), "+f"((d)[1]), "+f"((d)[2]), "+f"((d)[3]) \
        : "r"((a)[0]), "r"((a)[1]), "r"((a)[2]), "r"((a)[3]), "r"((b)[0]), "r"((b)[1]))

__device__ __forceinline__ uint32_t bfpack(__nv_bfloat16 a, __nv_bfloat16 b) {
    union { __nv_bfloat162 v; uint32_t u; } x;
    x.v = __halves2bfloat162(a, b);
    return x.u;
}

__device__ __forceinline__ void split2(float x0, float x1, uint32_t& h, uint32_t& l) {
    __nv_bfloat16 h0 = __float2bfloat16(x0), h1 = __float2bfloat16(x1);
    __nv_bfloat16 l0 = __float2bfloat16(x0 - __bfloat162float(h0));
    __nv_bfloat16 l1 = __float2bfloat16(x1 - __bfloat162float(h1));
    h = bfpack(h0, h1);
    l = bfpack(l0, l1);
}

// Load one 64-float global row, split to bf16 hi/lo padded smem rows; return sum of squares.
__device__ __forceinline__ float stage_row64(char* sm, int hiOff, int loOff,
                                             int row, const float* src) {
    float ss = 0.f;
    #pragma unroll
    for (int c = 0; c < 8; c++) {
        float4 a0 = *(const float4*)(src + c * 8);
        float4 a1 = *(const float4*)(src + c * 8 + 4);
        float v[8] = {a0.x, a0.y, a0.z, a0.w, a1.x, a1.y, a1.z, a1.w};
        uint32_t hw[4], lw[4];
        #pragma unroll
        for (int p = 0; p < 4; p++) {
            ss += v[2*p] * v[2*p] + v[2*p+1] * v[2*p+1];
            split2(v[2*p], v[2*p+1], hw[p], lw[p]);
        }
        int off = (row * STR + c * 8) * 2;
        *(uint4*)(sm + hiOff + off) = make_uint4(hw[0], hw[1], hw[2], hw[3]);
        *(uint4*)(sm + loOff + off) = make_uint4(lw[0], lw[1], lw[2], lw[3]);
    }
    return ss;
}

__global__ void __launch_bounds__(NT, 1)
dual_path_attn_mma(const float* __restrict__ gq,
                   const float* __restrict__ gk,
                   const float* __restrict__ gvd,
                   const float* __restrict__ gvw,
                   const float* __restrict__ gfg,
                   float* __restrict__ out)
{
    extern __shared__ char smem[];
    const uint32_t sb = smem_u32(smem);
    const int tid = threadIdx.x;
    const int wid = tid >> 5;
    const int ln  = tid & 31;
    const int tq  = ln >> 2;          // 0..7
    const int tr  = ln & 3;           // 0..3
    const int m0  = (wid & 3) * 32;   // warp row base
    const int n0  = (wid >> 2) * 32;  // warp col base
    const int wc  = wid >> 2;         // col-half 0/1

    const int bid = blockIdx.x;
    const int mb = bid & 15;          // L/128 = 16
    const int bh = bid >> 4;
    const int hh = bh & 7;
    const int b  = bh >> 3;
    const int l0 = mb * BM;

    float* QNp = (float*)(smem + SM_QN);
    float* KNp = (float*)(smem + SM_KN);
    float* LDp = (float*)(smem + SM_LD);
    float* LWp = (float*)(smem + SM_LW);
    float* REDp = (float*)(smem + SM_RED);

    // ---- Stage Q (once) ----
    if (tid < BM) {
        const float* src = gq + ((((size_t)b * L_ + l0 + tid) * H_ + hh) << 6);
        QNp[tid] = stage_row64(smem, QHI, QLO, tid, src);
    }
    __syncthreads();

    float qn[2][2];
    #pragma unroll
    for (int mi = 0; mi < 2; mi++)
        #pragma unroll
        for (int hf = 0; hf < 2; hf++)
            qn[mi][hf] = QNp[m0 + 16*mi + tq + 8*hf];

    // Persistent accumulators
    float od[2][4][4], ow[2][4][4];
    #pragma unroll
    for (int mi = 0; mi < 2; mi++)
        #pragma unroll
        for (int ni = 0; ni < 4; ni++)
            #pragma unroll
            for (int f = 0; f < 4; f++) { od[mi][ni][f] = 0.f; ow[mi][ni][f] = 0.f; }
    float ldacc[2][2] = {{0.f,0.f},{0.f,0.f}};
    float lwacc[2][2] = {{0.f,0.f},{0.f,0.f}};
    float regacc = 0.f;

    for (int t = 0; t < 32; t++) {
        __syncthreads();   // prior tile's readers done

        // ---- Stage K (+kn2) and Vd/Vw ([s][d] rows, split) ----
        const int s0 = t * 64;
        if (tid < 64) {
            const float* src = gk + ((((size_t)b * S_ + s0 + tid) * H_ + hh) << 6);
            KNp[tid] = stage_row64(smem, KHI, KLO, tid, src);
        } else if (tid < 128) {
            const int s = tid - 64;
            const float* src = gvd + ((((size_t)b * S_ + s0 + s) * H_ + hh) << 6);
            stage_row64(smem, VDH, VDL, s, src);
        } else if (tid < 192) {
            const int s = tid - 128;
            const float* src = gvw + ((((size_t)b * S_ + s0 + s) * H_ + hh) << 6);
            stage_row64(smem, VWH, VWL, s, src);
        }
        __syncthreads();

        // ---- Score MMAs: S = Qhi*Khi + Qhi*Klo + Qlo*Khi ----
        float sc[2][4][4];
        #pragma unroll
        for (int mi = 0; mi < 2; mi++)
            #pragma unroll
            for (int ni = 0; ni < 4; ni++)
                #pragma unroll
                for (int f = 0; f < 4; f++) sc[mi][ni][f] = 0.f;

        #pragma unroll
        for (int k = 0; k < 4; k++) {
            const int k0 = k * 16;
            uint32_t ah[2][4], al[2][4];
            const int arow = (ln & 15);
            const int akof = (ln >> 4) * 8;
            #pragma unroll
            for (int mi = 0; mi < 2; mi++) {
                uint32_t aoff = ((m0 + 16*mi + arow) * STR + k0 + akof) * 2;
                LDSM4(ah[mi][0], ah[mi][1], ah[mi][2], ah[mi][3], sb + QHI + aoff);
                LDSM4(al[mi][0], al[mi][1], al[mi][2], al[mi][3], sb + QLO + aoff);
            }
            uint32_t bhm[4][2], blm[4][2];
            const int brow = (ln & 7) + ((ln >> 4) & 1) * 8;
            const int bkof = ((ln >> 3) & 1) * 8;
            #pragma unroll
            for (int np = 0; np < 2; np++) {
                uint32_t boff = ((n0 + 16*np + brow) * STR + k0 + bkof) * 2;
                LDSM4(bhm[2*np][0], bhm[2*np][1], bhm[2*np+1][0], bhm[2*np+1][1], sb + KHI + boff);
                LDSM4(blm[2*np][0], blm[2*np][1], blm[2*np+1][0], blm[2*np+1][1], sb + KLO + boff);
            }
            #pragma unroll
            for (int mi = 0; mi < 2; mi++)
                #pragma unroll
                for (int ni = 0; ni < 4; ni++) {
                    MMA16816(sc[mi][ni], ah[mi], bhm[ni]);
                    MMA16816(sc[mi][ni], ah[mi], blm[ni]);
                    MMA16816(sc[mi][ni], al[mi], bhm[ni]);
                }
        }

        // ---- Epilogue: exp both paths (no max), split P to bf16 hi/lo smem ----
        float knv[4][2];
        #pragma unroll
        for (int ni = 0; ni < 4; ni++) {
            knv[ni][0] = KNp[n0 + 8*ni + 2*tr];
            knv[ni][1] = KNp[n0 + 8*ni + 2*tr + 1];
        }
        #pragma unroll
        for (int mi = 0; mi < 2; mi++) {
            #pragma unroll
            for (int ni = 0; ni < 4; ni++) {
                float pdv[4], pwv[4];
                #pragma unroll
                for (int f = 0; f < 4; f++) {
                    float d0 = sc[mi][ni][f];
                    float w2 = fmaxf(fmaf(-d0, d0, qn[mi][f>>1] * knv[ni][f&1]), 0.f) + EPS_;
                    float wr = sqrtf(w2);
                    float pd = __expf(d0 * SCALE_);
                    float pw = __expf(wr * SCALE_);
                    regacc += fabsf(d0) + wr;
                    ldacc[mi][f>>1] += pd;
                    lwacc[mi][f>>1] += pw;
                    pdv[f] = pd; pwv[f] = pw;
                }
                const int r0 = m0 + 16*mi + tq;
                const int c  = n0 + 8*ni + 2*tr;
                const int off0 = (r0 * STR + c) * 2;
                const int off1 = ((r0 + 8) * STR + c) * 2;
                uint32_t h0, l0w, h1, l1w;
                split2(pdv[0], pdv[1], h0, l0w);
                split2(pdv[2], pdv[3], h1, l1w);
                *(uint32_t*)(smem + PDH + off0) = h0;
                *(uint32_t*)(smem + PDL + off0) = l0w;
                *(uint32_t*)(smem + PDH + off1) = h1;
                *(uint32_t*)(smem + PDL + off1) = l1w;
                split2(pwv[0], pwv[1], h0, l0w);
                split2(pwv[2], pwv[3], h1, l1w);
                *(uint32_t*)(smem + PWH + off0) = h0;
                *(uint32_t*)(smem + PWL + off0) = l0w;
                *(uint32_t*)(smem + PWH + off1) = h1;
                *(uint32_t*)(smem + PWL + off1) = l1w;
            }
        }
        __syncthreads();

        // ---- PV MMAs: O += Phi*Vhi + Phi*Vlo + Plo*Vhi (both paths) ----
        #pragma unroll
        for (int k = 0; k < 4; k++) {
            const int k0 = k * 16;
            const int arow = (ln & 15);
            const int akof = (ln >> 4) * 8;
            const int vrow = k0 + (ln & 7) + ((ln >> 3) & 1) * 8;   // s index
            const int vcof = ((ln >> 4) & 1) * 8;                   // d offset
            // dot path
            {
                uint32_t pah[2][4], pal[2][4], vbh[4][2], vbl[4][2];
                #pragma unroll
                for (int mi = 0; mi < 2; mi++) {
                    uint32_t aoff = ((m0 + 16*mi + arow) * STR + k0 + akof) * 2;
                    LDSM4(pah[mi][0], pah[mi][1], pah[mi][2], pah[mi][3], sb + PDH + aoff);
                    LDSM4(pal[mi][0], pal[mi][1], pal[mi][2], pal[mi][3], sb + PDL + aoff);
                }
                #pragma unroll
                for (int np = 0; np < 2; np++) {
                    uint32_t boff = (vrow * STR + n0 + 16*np + vcof) * 2;
                    LDSM4T(vbh[2*np][0], vbh[2*np][1], vbh[2*np+1][0], vbh[2*np+1][1], sb + VDH + boff);
                    LDSM4T(vbl[2*np][0], vbl[2*np][1], vbl[2*np+1][0], vbl[2*np+1][1], sb + VDL + boff);
                }
                #pragma unroll
                for (int mi = 0; mi < 2; mi++)
                    #pragma unroll
                    for (int ni = 0; ni < 4; ni++) {
                        MMA16816(od[mi][ni], pah[mi], vbh[ni]);
                        MMA16816(od[mi][ni], pah[mi], vbl[ni]);
                        MMA16816(od[mi][ni], pal[mi], vbh[ni]);
                    }
            }
            // wedge path
            {
                uint32_t pah[2][4], pal[2][4], vbh[4][2], vbl[4][2];
                #pragma unroll
                for (int mi = 0; mi < 2; mi++) {
                    uint32_t aoff = ((m0 + 16*mi + arow) * STR + k0 + akof) * 2;
                    LDSM4(pah[mi][0], pah[mi][1], pah[mi][2], pah[mi][3], sb + PWH + aoff);
                    LDSM4(pal[mi][0], pal[mi][1], pal[mi][2], pal[mi][3], sb + PWL + aoff);
                }
                #pragma unroll
                for (int np = 0; np < 2; np++) {
                    uint32_t boff = (vrow * STR + n0 + 16*np + vcof) * 2;
                    LDSM4T(vbh[2*np][0], vbh[2*np][1], vbh[2*np+1][0], vbh[2*np+1][1], sb + VWH + boff);
                    LDSM4T(vbl[2*np][0], vbl[2*np][1], vbl[2*np+1][0], vbl[2*np+1][1], sb + VWL + boff);
                }
                #pragma unroll
                for (int mi = 0; mi < 2; mi++)
                    #pragma unroll
                    for (int ni = 0; ni < 4; ni++) {
                        MMA16816(ow[mi][ni], pah[mi], vbh[ni]);
                        MMA16816(ow[mi][ni], pah[mi], vbl[ni]);
                        MMA16816(ow[mi][ni], pal[mi], vbh[ni]);
                    }
            }
        }
    }

    // ---- Row denominators: reduce over quad (tr lanes), combine col halves ----
    #pragma unroll
    for (int mi = 0; mi < 2; mi++)
        #pragma unroll
        for (int hf = 0; hf < 2; hf++) {
            float vd = ldacc[mi][hf], vw = lwacc[mi][hf];
            vd += __shfl_xor_sync(0xffffffffu, vd, 1);
            vd += __shfl_xor_sync(0xffffffffu, vd, 2);
            vw += __shfl_xor_sync(0xffffffffu, vw, 1);
            vw += __shfl_xor_sync(0xffffffffu, vw, 2);
            if (tr == 0) {
                int r = m0 + 16*mi + tq + 8*hf;
                LDp[wc * 128 + r] = vd;
                LWp[wc * 128 + r] = vw;
            }
        }
    __syncthreads();

    // ---- Output: fuse paths ----
    const float fg = *gfg;
    const float g = 1.f / (1.f + __expf(-fg));
    #pragma unroll
    for (int mi = 0; mi < 2; mi++) {
        #pragma unroll
        for (int hf = 0; hf < 2; hf++) {
            const int r = m0 + 16*mi + tq + 8*hf;
            const float sd = (1.f - g) / (LDp[r] + LDp[128 + r]);
            const float sw = g / (LWp[r] + LWp[128 + r]);
            float* orow = out + ((((size_t)b * L_ + l0 + r) * H_ + hh) << 6);
            #pragma unroll
            for (int ni = 0; ni < 4; ni++) {
                float2 o;
                o.x = od[mi][ni][2*hf]     * sd + ow[mi][ni][2*hf]     * sw;
                o.y = od[mi][ni][2*hf + 1] * sd + ow[mi][ni][2*hf + 1] * sw;
                *(float2*)(orow + n0 + 8*ni + 2*tr) = o;
            }
        }
    }

    // ---- Deterministic regularizer partial ----
    REDp[tid] = regacc * SCALE_;
    __syncthreads();
    #pragma unroll
    for (int off = 128; off > 0; off >>= 1) {
        if (tid < off) REDp[tid] += REDp[tid + off];
        __syncthreads();
    }
    if (tid == 0) g_reg_partials[bid] = REDp[0];
}

// Deterministic fixed-order finalize of attn_reg
__global__ void finalize_reg_kernel(float* __restrict__ out)
{
    __shared__ float s[256];
    int tid = threadIdx.x;
    s[tid] = g_reg_partials[tid];
    __syncthreads();
    #pragma unroll
    for (int off = 128; off > 0; off >>= 1) {
        if (tid < off) s[tid] += s[tid + off];
        __syncthreads();
    }
    if (tid == 0) out[OUT_OFF] = s[0] * REG_NORM;
}

extern "C" void kernel_launch(void* const* d_in, const int* in_sizes, int n_in,
                              void* d_out, int out_size)
{
    const float* gq  = (const float*)d_in[0];
    const float* gk  = (const float*)d_in[1];
    const float* gvd = (const float*)d_in[2];
    const float* gvw = (const float*)d_in[3];
    const float* gfg = (const float*)d_in[4];
    float* out = (float*)d_out;

    static bool attr_set = false;
    if (!attr_set) {
        cudaFuncSetAttribute(dual_path_attn_mma,
                             cudaFuncAttributeMaxDynamicSharedMemorySize, SMEM_BYTES);
        attr_set = true;
    }

    dual_path_attn_mma<<<NBLOCKS, NT, SMEM_BYTES>>>(gq, gk, gvd, gvw, gfg, out);
    finalize_reg_kernel<<<1, 256>>>(out);
}

// round 6
// speedup vs baseline: 3.3391x; 1.2583x over previous
#include <cuda_runtime.h>
#include <cuda_bf16.h>
#include <cstdint>

// Problem constants
#define B_ 2
#define L_ 2048
#define S_ 2048
#define H_ 8

constexpr int BM = 128;               // query rows per CTA
constexpr int NT = 256;               // 8 warps
constexpr int NBLOCKS = B_ * H_ * (L_ / BM);   // 256
constexpr int OUT_OFF = B_ * L_ * H_ * 64;
constexpr float REG_NORM = 0.5f / ((float)B_ * H_ * L_ * S_);
constexpr float SCALE_ = 0.125f;
constexpr float EPS_   = 1e-8f;
constexpr int STR = 72;               // bf16 row stride (144 B, conflict-free ldmatrix)

// ---- Global bf16 scratch (pre-split hi/lo) + norms ----
constexpr int NELEM = B_ * S_ * H_ * 64;     // 2M elements per tensor
__device__ __align__(16) __nv_bfloat16 gQhi[NELEM], gQlo[NELEM];
__device__ __align__(16) __nv_bfloat16 gKhi[NELEM], gKlo[NELEM];
__device__ __align__(16) __nv_bfloat16 gVdhi[NELEM], gVdlo[NELEM];
__device__ __align__(16) __nv_bfloat16 gVwhi[NELEM], gVwlo[NELEM];
__device__ __align__(16) float gQN[B_ * H_ * L_];   // [b][h][l]
__device__ __align__(16) float gKN[B_ * H_ * S_];   // [b][h][s]
__device__ float g_reg_partials[NBLOCKS];

// ---- Shared memory byte offsets (main kernel) ----
constexpr int QHI = 0;                  // [128][72] bf16 = 18432
constexpr int QLO = 18432;
constexpr int PDH = 36864;              // P tiles [128][72] hi/lo x 2 paths
constexpr int PDL = 55296;
constexpr int PWH = 73728;
constexpr int PWL = 92160;
constexpr int KST = 110592;             // K stages: st*18432 (+0 hi, +9216 lo)
constexpr int VST = 147456;             // V stages: st*36864 (+0 VdH,+9216 VdL,+18432 VwH,+27648 VwL)
constexpr int SM_QN = 221184;           // 128 f32
constexpr int SM_KN = 221696;           // [2][64] f32
constexpr int SM_LD = 222208;           // [2][128] f32
constexpr int SM_LW = 223232;           // [2][128] f32
constexpr int SM_RED = 224256;          // 256 f32
constexpr int SMEM_BYTES = 225280;

__device__ __forceinline__ uint32_t smem_u32(const void* p) {
    uint32_t a;
    asm("{ .reg .u64 t; cvta.to.shared.u64 t, %1; cvt.u32.u64 %0, t; }" : "=r"(a) : "l"(p));
    return a;
}

#define CP16(dst, src)  asm volatile("cp.async.cg.shared.global [%0], [%1], 16;" :: "r"(dst), "l"(src))
#define CP_COMMIT()     asm volatile("cp.async.commit_group;" ::: "memory")
#define CP_WAIT1()      asm volatile("cp.async.wait_group 1;" ::: "memory")

#define LDSM4(r0,r1,r2,r3,addr) \
    asm volatile("ldmatrix.sync.aligned.m8n8.x4.shared.b16 {%0,%1,%2,%3}, [%4];" \
        : "=r"(r0), "=r"(r1), "=r"(r2), "=r"(r3) : "r"(addr))

#define LDSM4T(r0,r1,r2,r3,addr) \
    asm volatile("ldmatrix.sync.aligned.m8n8.x4.trans.shared.b16 {%0,%1,%2,%3}, [%4];" \
        : "=r"(r0), "=r"(r1), "=r"(r2), "=r"(r3) : "r"(addr))

#define MMA16816(d,a,b) \
    asm volatile("mma.sync.aligned.m16n8k16.row.col.f32.bf16.bf16.f32 " \
        "{%0,%1,%2,%3}, {%4,%5,%6,%7}, {%8,%9}, {%0,%1,%2,%3};" \
        : "+f"((d)[0]), "+f"((d)[1]), "+f"((d)[2]), "+f"((d)[3]) \
        : "r"((a)[0]), "r"((a)[1]), "r"((a)[2]), "r"((a)[3]), "r"((b)[0]), "r"((b)[1]))

__device__ __forceinline__ uint32_t bfpack(__nv_bfloat16 a, __nv_bfloat16 b) {
    union { __nv_bfloat162 v; uint32_t u; } x;
    x.v = __halves2bfloat162(a, b);
    return x.u;
}

__device__ __forceinline__ void split2(float x0, float x1, uint32_t& h, uint32_t& l) {
    __nv_bfloat16 h0 = __float2bfloat16(x0), h1 = __float2bfloat16(x1);
    __nv_bfloat16 l0 = __float2bfloat16(x0 - __bfloat162float(h0));
    __nv_bfloat16 l1 = __float2bfloat16(x1 - __bfloat162float(h1));
    h = bfpack(h0, h1);
    l = bfpack(l0, l1);
}

// ---- Pre-pass: split all 4 tensors to bf16 hi/lo, compute row norms ----
// One warp per 64-element row; 4 tensors x 32768 rows = 131072 warps.
__global__ void __launch_bounds__(256)
prepass_kernel(const float* __restrict__ gq,  const float* __restrict__ gk,
               const float* __restrict__ gvd, const float* __restrict__ gvw)
{
    const int wg = blockIdx.x * 8 + (threadIdx.x >> 5);
    const int lane = threadIdx.x & 31;
    const int tensor = wg >> 15;
    const int row = wg & 32767;              // (b*S + s)*H + h

    const float* src;
    __nv_bfloat16 *hi, *lo;
    float* norm = nullptr;
    if (tensor == 0)      { src = gq;  hi = gQhi;  lo = gQlo;  norm = gQN; }
    else if (tensor == 1) { src = gk;  hi = gKhi;  lo = gKlo;  norm = gKN; }
    else if (tensor == 2) { src = gvd; hi = gVdhi; lo = gVdlo; }
    else                  { src = gvw; hi = gVwhi; lo = gVwlo; }

    float2 x = ((const float2*)(src + (size_t)row * 64))[lane];
    uint32_t hw, lw;
    split2(x.x, x.y, hw, lw);
    ((uint32_t*)(hi + (size_t)row * 64))[lane] = hw;
    ((uint32_t*)(lo + (size_t)row * 64))[lane] = lw;

    if (norm) {
        float ss = x.x * x.x + x.y * x.y;
        #pragma unroll
        for (int off = 16; off >= 1; off >>= 1)
            ss += __shfl_xor_sync(0xffffffffu, ss, off);
        if (lane == 0) {
            int hh = row & 7, bs = row >> 3;
            int s = bs & 2047, b = bs >> 11;
            norm[(b * 8 + hh) * 2048 + s] = ss;
        }
    }
}

// ---- Prefetch one key-tile (K hi/lo, Vd/Vw hi/lo, kn2) into stage st ----
__device__ __forceinline__ void prefetch_tile(int t, int st, int tid, uint32_t sb,
                                              int b, int hh)
{
    const int s0 = t * 64;
    const size_t kbase = ((size_t)(b * S_ + s0) * H_ + hh) * 64;   // element offset, row stride H_*64
    #pragma unroll
    for (int u = 0; u < 4; u++) {                 // K: 1024 chunks
        int c = tid + u * NT;
        int half = c >> 9, row = (c >> 3) & 63, off = c & 7;
        const __nv_bfloat16* src = (half ? gKlo : gKhi) + kbase + (size_t)row * (H_ * 64) + off * 8;
        CP16(sb + KST + st * 18432 + half * 9216 + row * 144 + off * 16, src);
    }
    #pragma unroll
    for (int u = 0; u < 8; u++) {                 // V: 2048 chunks (VdH,VdL,VwH,VwL)
        int c = tid + u * NT;
        int th = c >> 9, row = (c >> 3) & 63, off = c & 7;
        const __nv_bfloat16* base = (th == 0) ? gVdhi : (th == 1) ? gVdlo : (th == 2) ? gVwhi : gVwlo;
        const __nv_bfloat16* src = base + kbase + (size_t)row * (H_ * 64) + off * 8;
        CP16(sb + VST + st * 36864 + th * 9216 + row * 144 + off * 16, src);
    }
    if (tid < 16)                                  // kn2: 64 floats
        CP16(sb + SM_KN + st * 256 + tid * 16, gKN + (size_t)(b * H_ + hh) * S_ + s0 + tid * 4);
}

__global__ void __launch_bounds__(NT, 1)
dual_path_attn_mma(const float* __restrict__ gfg, float* __restrict__ out)
{
    extern __shared__ char smem[];
    const uint32_t sb = smem_u32(smem);
    const int tid = threadIdx.x;
    const int wid = tid >> 5;
    const int ln  = tid & 31;
    const int tq  = ln >> 2;
    const int tr  = ln & 3;
    const int m0  = (wid & 3) * 32;
    const int n0  = (wid >> 2) * 32;
    const int wc  = wid >> 2;

    const int bid = blockIdx.x;
    const int mb = bid & 15;
    const int bh = bid >> 4;
    const int hh = bh & 7;
    const int b  = bh >> 3;
    const int l0 = mb * BM;

    float* QNp = (float*)(smem + SM_QN);
    float* LDp = (float*)(smem + SM_LD);
    float* LWp = (float*)(smem + SM_LW);
    float* REDp = (float*)(smem + SM_RED);

    // ---- Stage Q (bf16 hi/lo from scratch) + qn2, plus tile-0 prefetch ----
    {
        const size_t qbase = ((size_t)(b * L_ + l0) * H_ + hh) * 64;
        #pragma unroll
        for (int u = 0; u < 8; u++) {             // 2048 chunks
            int c = tid + u * NT;
            int half = c >> 10, row = (c >> 3) & 127, off = c & 7;
            const __nv_bfloat16* src = (half ? gQlo : gQhi) + qbase + (size_t)row * (H_ * 64) + off * 8;
            CP16(sb + (half ? QLO : QHI) + row * 144 + off * 16, src);
        }
        if (tid < 32)
            CP16(sb + SM_QN + tid * 16, gQN + (size_t)(b * H_ + hh) * L_ + l0 + tid * 4);
        prefetch_tile(0, 0, tid, sb, b, hh);
        CP_COMMIT();
    }

    // Persistent accumulators
    float od[2][4][4], ow[2][4][4];
    #pragma unroll
    for (int mi = 0; mi < 2; mi++)
        #pragma unroll
        for (int ni = 0; ni < 4; ni++)
            #pragma unroll
            for (int f = 0; f < 4; f++) { od[mi][ni][f] = 0.f; ow[mi][ni][f] = 0.f; }
    float ldacc[2][2] = {{0.f,0.f},{0.f,0.f}};
    float lwacc[2][2] = {{0.f,0.f},{0.f,0.f}};
    float regacc = 0.f;
    float qn[2][2];
    bool qn_loaded = false;

    for (int t = 0; t < 32; t++) {
        const int cur = t & 1;

        __syncthreads();   // readers of stage cur^1 (tile t-1) are done
        if (t < 31) prefetch_tile(t + 1, cur ^ 1, tid, sb, b, hh);
        CP_COMMIT();
        CP_WAIT1();        // tile t's group (and Q on t=0) complete
        __syncthreads();

        if (!qn_loaded) {
            #pragma unroll
            for (int mi = 0; mi < 2; mi++)
                #pragma unroll
                for (int hf = 0; hf < 2; hf++)
                    qn[mi][hf] = QNp[m0 + 16*mi + tq + 8*hf];
            qn_loaded = true;
        }
        const float* KNs = (const float*)(smem + SM_KN + cur * 256);
        const uint32_t kB = sb + KST + cur * 18432;         // K hi base
        const uint32_t vB = sb + VST + cur * 36864;         // Vd hi base

        // ---- Score MMAs: S = Qhi*Khi + Qhi*Klo + Qlo*Khi ----
        float sc[2][4][4];
        #pragma unroll
        for (int mi = 0; mi < 2; mi++)
            #pragma unroll
            for (int ni = 0; ni < 4; ni++)
                #pragma unroll
                for (int f = 0; f < 4; f++) sc[mi][ni][f] = 0.f;

        #pragma unroll
        for (int k = 0; k < 4; k++) {
            const int k0 = k * 16;
            uint32_t ah[2][4], al[2][4];
            const int arow = (ln & 15);
            const int akof = (ln >> 4) * 8;
            #pragma unroll
            for (int mi = 0; mi < 2; mi++) {
                uint32_t aoff = ((m0 + 16*mi + arow) * STR + k0 + akof) * 2;
                LDSM4(ah[mi][0], ah[mi][1], ah[mi][2], ah[mi][3], sb + QHI + aoff);
                LDSM4(al[mi][0], al[mi][1], al[mi][2], al[mi][3], sb + QLO + aoff);
            }
            uint32_t bhm[4][2], blm[4][2];
            const int brow = (ln & 7) + ((ln >> 4) & 1) * 8;
            const int bkof = ((ln >> 3) & 1) * 8;
            #pragma unroll
            for (int np = 0; np < 2; np++) {
                uint32_t boff = ((n0 + 16*np + brow) * STR + k0 + bkof) * 2;
                LDSM4(bhm[2*np][0], bhm[2*np][1], bhm[2*np+1][0], bhm[2*np+1][1], kB + boff);
                LDSM4(blm[2*np][0], blm[2*np][1], blm[2*np+1][0], blm[2*np+1][1], kB + 9216 + boff);
            }
            #pragma unroll
            for (int mi = 0; mi < 2; mi++)
                #pragma unroll
                for (int ni = 0; ni < 4; ni++) {
                    MMA16816(sc[mi][ni], ah[mi], bhm[ni]);
                    MMA16816(sc[mi][ni], ah[mi], blm[ni]);
                    MMA16816(sc[mi][ni], al[mi], bhm[ni]);
                }
        }

        // ---- Epilogue: exp both paths (no max), split P to bf16 hi/lo smem ----
        float knv[4][2];
        #pragma unroll
        for (int ni = 0; ni < 4; ni++) {
            knv[ni][0] = KNs[n0 + 8*ni + 2*tr];
            knv[ni][1] = KNs[n0 + 8*ni + 2*tr + 1];
        }
        #pragma unroll
        for (int mi = 0; mi < 2; mi++) {
            #pragma unroll
            for (int ni = 0; ni < 4; ni++) {
                float pdv[4], pwv[4];
                #pragma unroll
                for (int f = 0; f < 4; f++) {
                    float d0 = sc[mi][ni][f];
                    float w2 = fmaxf(fmaf(-d0, d0, qn[mi][f>>1] * knv[ni][f&1]), 0.f) + EPS_;
                    float wr = sqrtf(w2);
                    float pd = __expf(d0 * SCALE_);
                    float pw = __expf(wr * SCALE_);
                    regacc += fabsf(d0) + wr;
                    ldacc[mi][f>>1] += pd;
                    lwacc[mi][f>>1] += pw;
                    pdv[f] = pd; pwv[f] = pw;
                }
                const int r0 = m0 + 16*mi + tq;
                const int c  = n0 + 8*ni + 2*tr;
                const int off0 = (r0 * STR + c) * 2;
                const int off1 = ((r0 + 8) * STR + c) * 2;
                uint32_t h0, l0w, h1, l1w;
                split2(pdv[0], pdv[1], h0, l0w);
                split2(pdv[2], pdv[3], h1, l1w);
                *(uint32_t*)(smem + PDH + off0) = h0;
                *(uint32_t*)(smem + PDL + off0) = l0w;
                *(uint32_t*)(smem + PDH + off1) = h1;
                *(uint32_t*)(smem + PDL + off1) = l1w;
                split2(pwv[0], pwv[1], h0, l0w);
                split2(pwv[2], pwv[3], h1, l1w);
                *(uint32_t*)(smem + PWH + off0) = h0;
                *(uint32_t*)(smem + PWL + off0) = l0w;
                *(uint32_t*)(smem + PWH + off1) = h1;
                *(uint32_t*)(smem + PWL + off1) = l1w;
            }
        }
        __syncthreads();

        // ---- PV MMAs: O += Phi*Vhi + Phi*Vlo + Plo*Vhi (both paths) ----
        #pragma unroll
        for (int k = 0; k < 4; k++) {
            const int k0 = k * 16;
            const int arow = (ln & 15);
            const int akof = (ln >> 4) * 8;
            const int vrow = k0 + (ln & 7) + ((ln >> 3) & 1) * 8;
            const int vcof = ((ln >> 4) & 1) * 8;
            // dot path
            {
                uint32_t pah[2][4], pal[2][4], vbh[4][2], vbl[4][2];
                #pragma unroll
                for (int mi = 0; mi < 2; mi++) {
                    uint32_t aoff = ((m0 + 16*mi + arow) * STR + k0 + akof) * 2;
                    LDSM4(pah[mi][0], pah[mi][1], pah[mi][2], pah[mi][3], sb + PDH + aoff);
                    LDSM4(pal[mi][0], pal[mi][1], pal[mi][2], pal[mi][3], sb + PDL + aoff);
                }
                #pragma unroll
                for (int np = 0; np < 2; np++) {
                    uint32_t boff = (vrow * STR + n0 + 16*np + vcof) * 2;
                    LDSM4T(vbh[2*np][0], vbh[2*np][1], vbh[2*np+1][0], vbh[2*np+1][1], vB + boff);
                    LDSM4T(vbl[2*np][0], vbl[2*np][1], vbl[2*np+1][0], vbl[2*np+1][1], vB + 9216 + boff);
                }
                #pragma unroll
                for (int mi = 0; mi < 2; mi++)
                    #pragma unroll
                    for (int ni = 0; ni < 4; ni++) {
                        MMA16816(od[mi][ni], pah[mi], vbh[ni]);
                        MMA16816(od[mi][ni], pah[mi], vbl[ni]);
                        MMA16816(od[mi][ni], pal[mi], vbh[ni]);
                    }
            }
            // wedge path
            {
                uint32_t pah[2][4], pal[2][4], vbh[4][2], vbl[4][2];
                #pragma unroll
                for (int mi = 0; mi < 2; mi++) {
                    uint32_t aoff = ((m0 + 16*mi + arow) * STR + k0 + akof) * 2;
                    LDSM4(pah[mi][0], pah[mi][1], pah[mi][2], pah[mi][3], sb + PWH + aoff);
                    LDSM4(pal[mi][0], pal[mi][1], pal[mi][2], pal[mi][3], sb + PWL + aoff);
                }
                #pragma unroll
                for (int np = 0; np < 2; np++) {
                    uint32_t boff = (vrow * STR + n0 + 16*np + vcof) * 2;
                    LDSM4T(vbh[2*np][0], vbh[2*np][1], vbh[2*np+1][0], vbh[2*np+1][1], vB + 18432 + boff);
                    LDSM4T(vbl[2*np][0], vbl[2*np][1], vbl[2*np+1][0], vbl[2*np+1][1], vB + 27648 + boff);
                }
                #pragma unroll
                for (int mi = 0; mi < 2; mi++)
                    #pragma unroll
                    for (int ni = 0; ni < 4; ni++) {
                        MMA16816(ow[mi][ni], pah[mi], vbh[ni]);
                        MMA16816(ow[mi][ni], pah[mi], vbl[ni]);
                        MMA16816(ow[mi][ni], pal[mi], vbh[ni]);
                    }
            }
        }
    }

    // ---- Row denominators: reduce over quad, combine col halves ----
    #pragma unroll
    for (int mi = 0; mi < 2; mi++)
        #pragma unroll
        for (int hf = 0; hf < 2; hf++) {
            float vd = ldacc[mi][hf], vw = lwacc[mi][hf];
            vd += __shfl_xor_sync(0xffffffffu, vd, 1);
            vd += __shfl_xor_sync(0xffffffffu, vd, 2);
            vw += __shfl_xor_sync(0xffffffffu, vw, 1);
            vw += __shfl_xor_sync(0xffffffffu, vw, 2);
            if (tr == 0) {
                int r = m0 + 16*mi + tq + 8*hf;
                LDp[wc * 128 + r] = vd;
                LWp[wc * 128 + r] = vw;
            }
        }
    __syncthreads();

    // ---- Output: fuse paths ----
    const float fg = *gfg;
    const float g = 1.f / (1.f + __expf(-fg));
    #pragma unroll
    for (int mi = 0; mi < 2; mi++) {
        #pragma unroll
        for (int hf = 0; hf < 2; hf++) {
            const int r = m0 + 16*mi + tq + 8*hf;
            const float sd = (1.f - g) / (LDp[r] + LDp[128 + r]);
            const float sw = g / (LWp[r] + LWp[128 + r]);
            float* orow = out + ((((size_t)b * L_ + l0 + r) * H_ + hh) << 6);
            #pragma unroll
            for (int ni = 0; ni < 4; ni++) {
                float2 o;
                o.x = od[mi][ni][2*hf]     * sd + ow[mi][ni][2*hf]     * sw;
                o.y = od[mi][ni][2*hf + 1] * sd + ow[mi][ni][2*hf + 1] * sw;
                *(float2*)(orow + n0 + 8*ni + 2*tr) = o;
            }
        }
    }

    // ---- Deterministic regularizer partial ----
    REDp[tid] = regacc * SCALE_;
    __syncthreads();
    #pragma unroll
    for (int off = 128; off > 0; off >>= 1) {
        if (tid < off) REDp[tid] += REDp[tid + off];
        __syncthreads();
    }
    if (tid == 0) g_reg_partials[bid] = REDp[0];
}

// Deterministic fixed-order finalize of attn_reg
__global__ void finalize_reg_kernel(float* __restrict__ out)
{
    __shared__ float s[256];
    int tid = threadIdx.x;
    s[tid] = g_reg_partials[tid];
    __syncthreads();
    #pragma unroll
    for (int off = 128; off > 0; off >>= 1) {
        if (tid < off) s[tid] += s[tid + off];
        __syncthreads();
    }
    if (tid == 0) out[OUT_OFF] = s[0] * REG_NORM;
}

extern "C" void kernel_launch(void* const* d_in, const int* in_sizes, int n_in,
                              void* d_out, int out_size)
{
    const float* gq  = (const float*)d_in[0];
    const float* gk  = (const float*)d_in[1];
    const float* gvd = (const float*)d_in[2];
    const float* gvw = (const float*)d_in[3];
    const float* gfg = (const float*)d_in[4];
    float* out = (float*)d_out;

    static bool attr_set = false;
    if (!attr_set) {
        cudaFuncSetAttribute(dual_path_attn_mma,
                             cudaFuncAttributeMaxDynamicSharedMemorySize, SMEM_BYTES);
        attr_set = true;
    }

    prepass_kernel<<<16384, 256>>>(gq, gk, gvd, gvw);
    dual_path_attn_mma<<<NBLOCKS, NT, SMEM_BYTES>>>(gfg, out);
    finalize_reg_kernel<<<1, 256>>>(out);
}

// round 7
// speedup vs baseline: 3.4629x; 1.0371x over previous
#include <cuda_runtime.h>
#include <cuda_bf16.h>
#include <cstdint>

// Problem constants
#define B_ 2
#define L_ 2048
#define S_ 2048
#define H_ 8

constexpr int BM = 128;               // query rows per CTA
constexpr int NT = 256;               // 8 warps
constexpr int NBLOCKS = B_ * H_ * (L_ / BM);   // 256
constexpr int OUT_OFF = B_ * L_ * H_ * 64;
constexpr float REG_NORM = 0.5f / ((float)B_ * H_ * L_ * S_);
constexpr float SCALE_ = 0.125f;
constexpr float EPS_   = 1e-8f;
constexpr int STR = 72;               // bf16 row stride (144 B, conflict-free ldmatrix)

// ---- Global bf16 scratch (pre-split hi/lo) + norms ----
constexpr int NELEM = B_ * S_ * H_ * 64;
__device__ __align__(16) __nv_bfloat16 gQhi[NELEM], gQlo[NELEM];
__device__ __align__(16) __nv_bfloat16 gKhi[NELEM], gKlo[NELEM];
__device__ __align__(16) __nv_bfloat16 gVdhi[NELEM], gVdlo[NELEM];
__device__ __align__(16) __nv_bfloat16 gVwhi[NELEM], gVwlo[NELEM];
__device__ __align__(16) float gQN[B_ * H_ * L_];
__device__ __align__(16) float gKN[B_ * H_ * S_];
__device__ float g_reg_partials[NBLOCKS];

// ---- Shared memory byte offsets (main kernel) ----
constexpr int QHI = 0;                  // [128][72] bf16 = 18432
constexpr int QLO = 18432;
constexpr int KST = 36864;              // K stages: +st*18432 (+0 hi, +9216 lo)
constexpr int VST = 73728;              // V stages: +st*36864 (+0 VdH,+9216 VdL,+18432 VwH,+27648 VwL)
constexpr int SM_QN = 147456;           // 128 f32
constexpr int SM_KN = 147968;           // [2][64] f32
constexpr int SM_RED = 148480;          // 256 f32
constexpr int SMEM_BYTES = 149504;

__device__ __forceinline__ uint32_t smem_u32(const void* p) {
    uint32_t a;
    asm("{ .reg .u64 t; cvta.to.shared.u64 t, %1; cvt.u32.u64 %0, t; }" : "=r"(a) : "l"(p));
    return a;
}

#define CP16(dst, src)  asm volatile("cp.async.cg.shared.global [%0], [%1], 16;" :: "r"(dst), "l"(src))
#define CP_COMMIT()     asm volatile("cp.async.commit_group;" ::: "memory")
#define CP_WAIT1()      asm volatile("cp.async.wait_group 1;" ::: "memory")

#define LDSM4(r0,r1,r2,r3,addr) \
    asm volatile("ldmatrix.sync.aligned.m8n8.x4.shared.b16 {%0,%1,%2,%3}, [%4];" \
        : "=r"(r0), "=r"(r1), "=r"(r2), "=r"(r3) : "r"(addr))

#define LDSM4T(r0,r1,r2,r3,addr) \
    asm volatile("ldmatrix.sync.aligned.m8n8.x4.trans.shared.b16 {%0,%1,%2,%3}, [%4];" \
        : "=r"(r0), "=r"(r1), "=r"(r2), "=r"(r3) : "r"(addr))

#define MMA16816(d,a,b) \
    asm volatile("mma.sync.aligned.m16n8k16.row.col.f32.bf16.bf16.f32 " \
        "{%0,%1,%2,%3}, {%4,%5,%6,%7}, {%8,%9}, {%0,%1,%2,%3};" \
        : "+f"((d)[0]), "+f"((d)[1]), "+f"((d)[2]), "+f"((d)[3]) \
        : "r"((a)[0]), "r"((a)[1]), "r"((a)[2]), "r"((a)[3]), "r"((b)[0]), "r"((b)[1]))

__device__ __forceinline__ uint32_t bfpack(__nv_bfloat16 a, __nv_bfloat16 b) {
    union { __nv_bfloat162 v; uint32_t u; } x;
    x.v = __halves2bfloat162(a, b);
    return x.u;
}

__device__ __forceinline__ void split2(float x0, float x1, uint32_t& h, uint32_t& l) {
    __nv_bfloat16 h0 = __float2bfloat16(x0), h1 = __float2bfloat16(x1);
    __nv_bfloat16 l0 = __float2bfloat16(x0 - __bfloat162float(h0));
    __nv_bfloat16 l1 = __float2bfloat16(x1 - __bfloat162float(h1));
    h = bfpack(h0, h1);
    l = bfpack(l0, l1);
}

// ---- Pre-pass: split all 4 tensors to bf16 hi/lo, compute row norms ----
__global__ void __launch_bounds__(256)
prepass_kernel(const float* __restrict__ gq,  const float* __restrict__ gk,
               const float* __restrict__ gvd, const float* __restrict__ gvw)
{
    const int wg = blockIdx.x * 8 + (threadIdx.x >> 5);
    const int lane = threadIdx.x & 31;
    const int tensor = wg >> 15;
    const int row = wg & 32767;

    const float* src;
    __nv_bfloat16 *hi, *lo;
    float* norm = nullptr;
    if (tensor == 0)      { src = gq;  hi = gQhi;  lo = gQlo;  norm = gQN; }
    else if (tensor == 1) { src = gk;  hi = gKhi;  lo = gKlo;  norm = gKN; }
    else if (tensor == 2) { src = gvd; hi = gVdhi; lo = gVdlo; }
    else                  { src = gvw; hi = gVwhi; lo = gVwlo; }

    float2 x = ((const float2*)(src + (size_t)row * 64))[lane];
    uint32_t hw, lw;
    split2(x.x, x.y, hw, lw);
    ((uint32_t*)(hi + (size_t)row * 64))[lane] = hw;
    ((uint32_t*)(lo + (size_t)row * 64))[lane] = lw;

    if (norm) {
        float ss = x.x * x.x + x.y * x.y;
        #pragma unroll
        for (int off = 16; off >= 1; off >>= 1)
            ss += __shfl_xor_sync(0xffffffffu, ss, off);
        if (lane == 0) {
            int hh = row & 7, bs = row >> 3;
            int s = bs & 2047, b = bs >> 11;
            norm[(b * 8 + hh) * 2048 + s] = ss;
        }
    }
}

// ---- Prefetch one key-tile (K hi/lo, Vd/Vw hi/lo, kn2) into stage st ----
__device__ __forceinline__ void prefetch_tile(int t, int st, int tid, uint32_t sb,
                                              int b, int hh)
{
    const int s0 = t * 64;
    const size_t kbase = ((size_t)(b * S_ + s0) * H_ + hh) * 64;
    #pragma unroll
    for (int u = 0; u < 4; u++) {                 // K: 1024 chunks
        int c = tid + u * NT;
        int half = c >> 9, row = (c >> 3) & 63, off = c & 7;
        const __nv_bfloat16* src = (half ? gKlo : gKhi) + kbase + (size_t)row * (H_ * 64) + off * 8;
        CP16(sb + KST + st * 18432 + half * 9216 + row * 144 + off * 16, src);
    }
    #pragma unroll
    for (int u = 0; u < 8; u++) {                 // V: 2048 chunks
        int c = tid + u * NT;
        int th = c >> 9, row = (c >> 3) & 63, off = c & 7;
        const __nv_bfloat16* base = (th == 0) ? gVdhi : (th == 1) ? gVdlo : (th == 2) ? gVwhi : gVwlo;
        const __nv_bfloat16* src = base + kbase + (size_t)row * (H_ * 64) + off * 8;
        CP16(sb + VST + st * 36864 + th * 9216 + row * 144 + off * 16, src);
    }
    if (tid < 16)
        CP16(sb + SM_KN + st * 256 + tid * 16, gKN + (size_t)(b * H_ + hh) * S_ + s0 + tid * 4);
}

__global__ void __launch_bounds__(NT, 1)
dual_path_attn_mma(const float* __restrict__ gfg, float* __restrict__ out)
{
    extern __shared__ char smem[];
    const uint32_t sb = smem_u32(smem);
    const int tid = threadIdx.x;
    const int wid = tid >> 5;
    const int ln  = tid & 31;
    const int tq  = ln >> 2;
    const int tr  = ln & 3;
    const int m0  = wid * 16;         // warp owns 16 rows x all 64 cols

    const int bid = blockIdx.x;
    const int mb = bid & 15;
    const int bh = bid >> 4;
    const int hh = bh & 7;
    const int b  = bh >> 3;
    const int l0 = mb * BM;

    float* QNp = (float*)(smem + SM_QN);
    float* REDp = (float*)(smem + SM_RED);

    // ---- Stage Q (bf16 hi/lo) + qn2 + tile-0 prefetch ----
    {
        const size_t qbase = ((size_t)(b * L_ + l0) * H_ + hh) * 64;
        #pragma unroll
        for (int u = 0; u < 8; u++) {
            int c = tid + u * NT;
            int half = c >> 10, row = (c >> 3) & 127, off = c & 7;
            const __nv_bfloat16* src = (half ? gQlo : gQhi) + qbase + (size_t)row * (H_ * 64) + off * 8;
            CP16(sb + (half ? QLO : QHI) + row * 144 + off * 16, src);
        }
        if (tid < 32)
            CP16(sb + SM_QN + tid * 16, gQN + (size_t)(b * H_ + hh) * L_ + l0 + tid * 4);
        prefetch_tile(0, 0, tid, sb, b, hh);
        CP_COMMIT();
    }

    // Persistent O accumulators: [path][ni][frag]
    float od[8][4], ow[8][4];
    #pragma unroll
    for (int ni = 0; ni < 8; ni++)
        #pragma unroll
        for (int f = 0; f < 4; f++) { od[ni][f] = 0.f; ow[ni][f] = 0.f; }
    float ldacc[2] = {0.f, 0.f}, lwacc[2] = {0.f, 0.f};
    float regacc = 0.f;
    float qn[2];
    bool qn_loaded = false;

    const int arow = (ln & 15);
    const int akof = (ln >> 4) * 8;
    const int brow = (ln & 7) + ((ln >> 4) & 1) * 8;
    const int bkof = ((ln >> 3) & 1) * 8;

    for (int t = 0; t < 32; t++) {
        const int cur = t & 1;

        __syncthreads();   // readers of stage cur^1 (tile t-1) done
        if (t < 31) prefetch_tile(t + 1, cur ^ 1, tid, sb, b, hh);
        CP_COMMIT();
        CP_WAIT1();        // tile t's group complete
        __syncthreads();

        if (!qn_loaded) {
            qn[0] = QNp[m0 + tq];
            qn[1] = QNp[m0 + tq + 8];
            qn_loaded = true;
        }
        const float* KNs = (const float*)(smem + SM_KN + cur * 256);
        const uint32_t kB = sb + KST + cur * 18432;
        const uint32_t vB = sb + VST + cur * 36864;

        // ---- Score MMAs: S = Qhi*Khi + Qhi*Klo + Qlo*Khi ----
        float sc[8][4];
        #pragma unroll
        for (int ni = 0; ni < 8; ni++)
            #pragma unroll
            for (int f = 0; f < 4; f++) sc[ni][f] = 0.f;

        #pragma unroll
        for (int k = 0; k < 4; k++) {
            const int k0 = k * 16;
            uint32_t ah[4], al[4];
            uint32_t aoff = ((m0 + arow) * STR + k0 + akof) * 2;
            LDSM4(ah[0], ah[1], ah[2], ah[3], sb + QHI + aoff);
            LDSM4(al[0], al[1], al[2], al[3], sb + QLO + aoff);
            uint32_t bhm[8][2], blm[8][2];
            #pragma unroll
            for (int np = 0; np < 4; np++) {
                uint32_t boff = ((np * 16 + brow) * STR + k0 + bkof) * 2;
                LDSM4(bhm[2*np][0], bhm[2*np][1], bhm[2*np+1][0], bhm[2*np+1][1], kB + boff);
                LDSM4(blm[2*np][0], blm[2*np][1], blm[2*np+1][0], blm[2*np+1][1], kB + 9216 + boff);
            }
            #pragma unroll
            for (int ni = 0; ni < 8; ni++) {
                MMA16816(sc[ni], ah, bhm[ni]);
                MMA16816(sc[ni], ah, blm[ni]);
                MMA16816(sc[ni], al, bhm[ni]);
            }
        }

        // ---- Epilogue: exp both paths (no max), P packed to A-fragments in regs ----
        uint32_t pahd[4][4], pald[4][4], pahw[4][4], palw[4][4];
        #pragma unroll
        for (int ni = 0; ni < 8; ni++) {
            float pdv[4], pwv[4];
            #pragma unroll
            for (int f = 0; f < 4; f++) {
                float d0 = sc[ni][f];
                float kn = KNs[8*ni + 2*tr + (f & 1)];
                float w2 = fmaxf(fmaf(-d0, d0, qn[f>>1] * kn), 0.f) + EPS_;
                float wr = sqrtf(w2);
                float pd = __expf(d0 * SCALE_);
                float pw = __expf(wr * SCALE_);
                regacc += fabsf(d0) + wr;
                ldacc[f>>1] += pd;
                lwacc[f>>1] += pw;
                pdv[f] = pd; pwv[f] = pw;
            }
            const int kk = ni >> 1, h2 = (ni & 1) * 2;
            split2(pdv[0], pdv[1], pahd[kk][h2],     pald[kk][h2]);
            split2(pdv[2], pdv[3], pahd[kk][h2 + 1], pald[kk][h2 + 1]);
            split2(pwv[0], pwv[1], pahw[kk][h2],     palw[kk][h2]);
            split2(pwv[2], pwv[3], pahw[kk][h2 + 1], palw[kk][h2 + 1]);
        }

        // ---- PV MMAs: O += Phi*Vhi + Phi*Vlo + Plo*Vhi (P from registers) ----
        const int vrow0 = (ln & 7) + ((ln >> 3) & 1) * 8;
        const int vcof = ((ln >> 4) & 1) * 8;
        #pragma unroll
        for (int k = 0; k < 4; k++) {
            const int vrow = k * 16 + vrow0;
            uint32_t vbh[8][2], vbl[8][2];
            #pragma unroll
            for (int np = 0; np < 4; np++) {
                uint32_t boff = (vrow * STR + np * 16 + vcof) * 2;
                LDSM4T(vbh[2*np][0], vbh[2*np][1], vbh[2*np+1][0], vbh[2*np+1][1], vB + boff);
                LDSM4T(vbl[2*np][0], vbl[2*np][1], vbl[2*np+1][0], vbl[2*np+1][1], vB + 9216 + boff);
            }
            #pragma unroll
            for (int ni = 0; ni < 8; ni++) {
                MMA16816(od[ni], pahd[k], vbh[ni]);
                MMA16816(od[ni], pahd[k], vbl[ni]);
                MMA16816(od[ni], pald[k], vbh[ni]);
            }
            #pragma unroll
            for (int np = 0; np < 4; np++) {
                uint32_t boff = (vrow * STR + np * 16 + vcof) * 2;
                LDSM4T(vbh[2*np][0], vbh[2*np][1], vbh[2*np+1][0], vbh[2*np+1][1], vB + 18432 + boff);
                LDSM4T(vbl[2*np][0], vbl[2*np][1], vbl[2*np+1][0], vbl[2*np+1][1], vB + 27648 + boff);
            }
            #pragma unroll
            for (int ni = 0; ni < 8; ni++) {
                MMA16816(ow[ni], pahw[k], vbh[ni]);
                MMA16816(ow[ni], pahw[k], vbl[ni]);
                MMA16816(ow[ni], palw[k], vbh[ni]);
            }
        }
    }

    // ---- Row denominators: reduce over quad (tr lanes only — warp owns full rows) ----
    #pragma unroll
    for (int hf = 0; hf < 2; hf++) {
        ldacc[hf] += __shfl_xor_sync(0xffffffffu, ldacc[hf], 1);
        ldacc[hf] += __shfl_xor_sync(0xffffffffu, ldacc[hf], 2);
        lwacc[hf] += __shfl_xor_sync(0xffffffffu, lwacc[hf], 1);
        lwacc[hf] += __shfl_xor_sync(0xffffffffu, lwacc[hf], 2);
    }

    // ---- Output: fuse paths ----
    const float fg = *gfg;
    const float g = 1.f / (1.f + __expf(-fg));
    #pragma unroll
    for (int hf = 0; hf < 2; hf++) {
        const int r = m0 + tq + 8 * hf;
        const float sd = (1.f - g) / ldacc[hf];
        const float sw = g / lwacc[hf];
        float* orow = out + ((((size_t)b * L_ + l0 + r) * H_ + hh) << 6);
        #pragma unroll
        for (int ni = 0; ni < 8; ni++) {
            float2 o;
            o.x = od[ni][2*hf]     * sd + ow[ni][2*hf]     * sw;
            o.y = od[ni][2*hf + 1] * sd + ow[ni][2*hf + 1] * sw;
            *(float2*)(orow + 8*ni + 2*tr) = o;
        }
    }

    // ---- Deterministic regularizer partial ----
    REDp[tid] = regacc * SCALE_;
    __syncthreads();
    #pragma unroll
    for (int off = 128; off > 0; off >>= 1) {
        if (tid < off) REDp[tid] += REDp[tid + off];
        __syncthreads();
    }
    if (tid == 0) g_reg_partials[bid] = REDp[0];
}

// Deterministic fixed-order finalize of attn_reg
__global__ void finalize_reg_kernel(float* __restrict__ out)
{
    __shared__ float s[256];
    int tid = threadIdx.x;
    s[tid] = g_reg_partials[tid];
    __syncthreads();
    #pragma unroll
    for (int off = 128; off > 0; off >>= 1) {
        if (tid < off) s[tid] += s[tid + off];
        __syncthreads();
    }
    if (tid == 0) out[OUT_OFF] = s[0] * REG_NORM;
}

extern "C" void kernel_launch(void* const* d_in, const int* in_sizes, int n_in,
                              void* d_out, int out_size)
{
    const float* gq  = (const float*)d_in[0];
    const float* gk  = (const float*)d_in[1];
    const float* gvd = (const float*)d_in[2];
    const float* gvw = (const float*)d_in[3];
    const float* gfg = (const float*)d_in[4];
    float* out = (float*)d_out;

    static bool attr_set = false;
    if (!attr_set) {
        cudaFuncSetAttribute(dual_path_attn_mma,
                             cudaFuncAttributeMaxDynamicSharedMemorySize, SMEM_BYTES);
        attr_set = true;
    }

    prepass_kernel<<<16384, 256>>>(gq, gk, gvd, gvw);
    dual_path_attn_mma<<<NBLOCKS, NT, SMEM_BYTES>>>(gfg, out);
    finalize_reg_kernel<<<1, 256>>>(out);
}